// round 6
// baseline (speedup 1.0000x reference)
#include <cuda_runtime.h>
#include <math.h>

#define B    32
#define C    3
#define H    512
#define W    512
#define TX   64               // output tile width
#define TY   32               // output tile height
#define RW   76               // res smem row stride (float4-aligned, 72 used)
#define RH   38               // res rows (TY + 6)
#define VW   73               // v1/v2 row stride (odd -> conflict-free column walks)
#define TILES_PER_IMG 128     // (512/64)*(512/32)

__device__ float g_psum  [B * TILES_PER_IMG];
__device__ float g_psumsq[B * TILES_PER_IMG];
__device__ float g_pS    [B * TILES_PER_IMG];

__global__ __launch_bounds__(256, 6)
void ldl_main(const float* __restrict__ net, const float* __restrict__ gt) {
    __shared__ float res[RH][RW];      // residual, col c <-> gx = 64*bx-4+c
    __shared__ float v1 [TY][VW];      // vertical 7-sums of r   (cols 1..70)
    __shared__ float v2 [TY][VW];      // vertical 7-sums of r^2
    __shared__ float red[3][8];

    const int bx  = blockIdx.x;        // 0..7
    const int by  = blockIdx.y;        // 0..15
    const int b   = blockIdx.z;
    const int tid = threadIdx.x;

    const int x0a = TX * bx - 4;       // global x of smem col 0 (16B aligned)
    const int y0a = TY * by - 3;       // global y of smem row 0

    const int HW = H * W;
    const float* nb = net + b * (C * HW);
    const float* gb = gt  + b * (C * HW);

    // ---- Phase 1: vectorized residual load (skip out-of-range vec4s) ----
    for (int i = tid; i < RH * 18; i += 256) {
        int row = i / 18, v = i - row * 18;
        int gy = y0a + row;
        int gx = x0a + 4 * v;          // multiple of 4 -> vec4 fully in or out
        if ((unsigned)gy < H && (unsigned)gx < W) {
            int p = gy * W + gx;
            float4 n0 = *(const float4*)(nb + p);
            float4 n1 = *(const float4*)(nb + p + HW);
            float4 n2 = *(const float4*)(nb + p + 2 * HW);
            float4 g0 = *(const float4*)(gb + p);
            float4 g1 = *(const float4*)(gb + p + HW);
            float4 g2 = *(const float4*)(gb + p + 2 * HW);
            float4 r;
            r.x = fabsf(g0.x - n0.x) + fabsf(g1.x - n1.x) + fabsf(g2.x - n2.x);
            r.y = fabsf(g0.y - n0.y) + fabsf(g1.y - n1.y) + fabsf(g2.y - n2.y);
            r.z = fabsf(g0.z - n0.z) + fabsf(g1.z - n1.z) + fabsf(g2.z - n2.z);
            r.w = fabsf(g0.w - n0.w) + fabsf(g1.w - n1.w) + fabsf(g2.w - n2.w);
            *(float4*)&res[row][4 * v] = r;
        }
    }
    __syncthreads();

    // ---- Phase 1b: reflect fixups (sources always inside the tile) ----
    if (by == 0) {                     // rows 0,1,2 <- rows 6,5,4
        for (int i = tid; i < 3 * 18; i += 256) {
            int r = i / 18, v = i - r * 18;
            *(float4*)&res[r][4 * v] = *(const float4*)&res[6 - r][4 * v];
        }
    }
    if (by == 15) {                    // rows 35,36,37 <- rows 33,32,31
        for (int i = tid; i < 3 * 18; i += 256) {
            int r = 35 + i / 18, v = i % 18;
            *(float4*)&res[r][4 * v] = *(const float4*)&res[68 - r][4 * v];
        }
    }
    __syncthreads();
    if (bx == 0) {                     // cols 1,2,3 <- cols 7,6,5
        for (int i = tid; i < RH * 3; i += 256) {
            int r = i / 3, c = 1 + i % 3;
            res[r][c] = res[r][8 - c];
        }
    }
    if (bx == 7) {                     // cols 68,69,70 <- cols 66,65,64
        for (int i = tid; i < RH * 3; i += 256) {
            int r = i / 3, c = 68 + i % 3;
            res[r][c] = res[r][134 - c];   // gx' = 1022 - gx  =>  c' = 134 - c
        }
    }
    __syncthreads();

    // ---- Phase 2': vertical sliding 7-sum (read each res row ONCE) ----
    // 70 cols x 4 groups of 8 output rows = 280 tasks
    for (int t = tid; t < 280; t += 256) {
        int col = t % 70 + 1;          // 1..70
        int y0  = (t / 70) * 8;        // 0,8,16,24

        float w1[7], w2[7];
        float s1 = 0.f, s2 = 0.f;
        #pragma unroll
        for (int d = 0; d < 7; d++) {
            float v = res[y0 + d][col];
            w1[d] = v; w2[d] = v * v;
            s1 += w1[d]; s2 += w2[d];
        }
        v1[y0][col] = s1; v2[y0][col] = s2;
        #pragma unroll
        for (int j = 1; j < 8; j++) {
            float v = res[y0 + 6 + j][col];
            s1 += v - w1[j - 1];
            s2 += v * v - w2[j - 1];
            v1[y0 + j][col] = s1;
            v2[y0 + j][col] = s2;
        }
    }
    __syncthreads();

    // ---- Phase 3': horizontal sliding 7-sum, 8 outputs per thread ----
    const int w  = tid >> 5, l = tid & 31;
    const int y  = (w & 3) * 8 + (l >> 2);       // 0..31
    const int g  = (w >> 2) * 4 + (l & 3);       // 0..7
    const int cb = 1 + 8 * g;                    // first tap column

    float a1[7], a2[7];
    float s1 = 0.f, s2 = 0.f;
    #pragma unroll
    for (int d = 0; d < 7; d++) {
        a1[d] = v1[y][cb + d];
        a2[d] = v2[y][cb + d];
        s1 += a1[d]; s2 += a2[d];
    }
    float accS = 0.f, accSum = 0.f, accSq = 0.f;
    #pragma unroll
    for (int j = 0; j < 8; j++) {
        float pw  = (s2 - s1 * s1 * (1.0f / 49.0f)) * (1.0f / 48.0f);
        float cen = res[y + 3][4 + 8 * g + j];
        accS   += fabsf(pw) * cen;
        accSum += cen;
        accSq  += cen * cen;
        if (j < 7) {
            s1 += v1[y][cb + 7 + j] - a1[j];
            s2 += v2[y][cb + 7 + j] - a2[j];
        }
    }

    // ---- block reduction ----
    #pragma unroll
    for (int off = 16; off; off >>= 1) {
        accS   += __shfl_down_sync(0xFFFFFFFFu, accS,   off);
        accSum += __shfl_down_sync(0xFFFFFFFFu, accSum, off);
        accSq  += __shfl_down_sync(0xFFFFFFFFu, accSq,  off);
    }
    if (l == 0) { red[0][w] = accS; red[1][w] = accSum; red[2][w] = accSq; }
    __syncthreads();
    if (tid == 0) {
        float S = 0.f, Su = 0.f, Sq = 0.f;
        #pragma unroll
        for (int k = 0; k < 8; k++) { S += red[0][k]; Su += red[1][k]; Sq += red[2][k]; }
        int tile = by * 8 + bx;
        g_pS    [b * TILES_PER_IMG + tile] = S;
        g_psum  [b * TILES_PER_IMG + tile] = Su;
        g_psumsq[b * TILES_PER_IMG + tile] = Sq;
    }
}

// Single-block epilogue: each warp handles 4 batches (parallel pow), then sum.
__global__ __launch_bounds__(256)
void ldl_final(float* __restrict__ out) {
    __shared__ double sh[8];
    const int tid = threadIdx.x;
    const int w = tid >> 5, lane = tid & 31;

    double tot = 0.0;
    for (int b = w; b < B; b += 8) {
        double dS = 0.0, dsu = 0.0, dsq = 0.0;
        #pragma unroll
        for (int k = 0; k < 4; k++) {
            int idx = b * TILES_PER_IMG + lane + 32 * k;
            dS  += (double)g_pS    [idx];
            dsu += (double)g_psum  [idx];
            dsq += (double)g_psumsq[idx];
        }
        #pragma unroll
        for (int off = 16; off; off >>= 1) {
            dS  += __shfl_down_sync(0xFFFFFFFFu, dS,  off);
            dsu += __shfl_down_sync(0xFFFFFFFFu, dsu, off);
            dsq += __shfl_down_sync(0xFFFFFFFFu, dsq, off);
        }
        if (lane == 0) {
            const double N = (double)(H * W);
            double var = (dsq - dsu * dsu / N) / (N - 1.0);
            if (var < 0.0) var = 0.0;
            tot += pow(var, 0.2) * dS;
        }
    }
    if (lane == 0) sh[w] = tot;
    __syncthreads();
    if (tid == 0) {
        double v = 0.0;
        #pragma unroll
        for (int k = 0; k < 8; k++) v += sh[k];
        out[0] = (float)(v / ((double)B * C * H * W));
    }
}

extern "C" void kernel_launch(void* const* d_in, const int* in_sizes, int n_in,
                              void* d_out, int out_size) {
    const float* net = (const float*)d_in[0];   // net_output
    const float* gt  = (const float*)d_in[1];   // gt
    float* out = (float*)d_out;

    dim3 grid(W / TX, H / TY, B);               // 8 x 16 x 32
    ldl_main<<<grid, 256>>>(net, gt);
    ldl_final<<<1, 256>>>(out);
}

// round 7
// speedup vs baseline: 1.3151x; 1.3151x over previous
#include <cuda_runtime.h>
#include <math.h>

#define B    32
#define C    3
#define H    512
#define W    512
#define TX   64               // output tile width
#define TY   32               // output tile height
#define RW   76               // res smem row stride (float4-aligned, 72 used)
#define RH   38               // res rows (TY + 6)
#define VW   73               // v1/v2 row stride (odd -> conflict-free column walks)
#define TILES_PER_IMG 128     // (512/64)*(512/32)
#define NBLOCKS (8 * 16 * 32) // 4096

__device__ float g_psum  [B * TILES_PER_IMG];
__device__ float g_psumsq[B * TILES_PER_IMG];
__device__ float g_pS    [B * TILES_PER_IMG];
__device__ unsigned g_count = 0;

__global__ __launch_bounds__(256, 6)
void ldl_main(const float* __restrict__ net, const float* __restrict__ gt,
              float* __restrict__ out) {
    __shared__ float res[RH][RW];      // residual, col c <-> gx = 64*bx-4+c
    __shared__ float v1 [TY][VW];      // vertical 7-sums of r   (cols 1..70)
    __shared__ float v2 [TY][VW];      // vertical 7-sums of r^2
    __shared__ float red[3][8];
    __shared__ double shd[8];
    __shared__ int s_last;

    const int bx  = blockIdx.x;        // 0..7
    const int by  = blockIdx.y;        // 0..15
    const int b   = blockIdx.z;
    const int tid = threadIdx.x;

    const int x0a = TX * bx - 4;       // global x of smem col 0 (16B aligned)
    const int y0a = TY * by - 3;       // global y of smem row 0

    const int HW = H * W;
    const float* nb = net + b * (C * HW);
    const float* gb = gt  + b * (C * HW);

    // ---- Phase 1: vectorized residual load (skip out-of-range vec4s) ----
    for (int i = tid; i < RH * 18; i += 256) {
        int row = i / 18, v = i - row * 18;
        int gy = y0a + row;
        int gx = x0a + 4 * v;          // multiple of 4 -> vec4 fully in or out
        if ((unsigned)gy < H && (unsigned)gx < W) {
            int p = gy * W + gx;
            float4 n0 = *(const float4*)(nb + p);
            float4 n1 = *(const float4*)(nb + p + HW);
            float4 n2 = *(const float4*)(nb + p + 2 * HW);
            float4 g0 = *(const float4*)(gb + p);
            float4 g1 = *(const float4*)(gb + p + HW);
            float4 g2 = *(const float4*)(gb + p + 2 * HW);
            float4 r;
            r.x = fabsf(g0.x - n0.x) + fabsf(g1.x - n1.x) + fabsf(g2.x - n2.x);
            r.y = fabsf(g0.y - n0.y) + fabsf(g1.y - n1.y) + fabsf(g2.y - n2.y);
            r.z = fabsf(g0.z - n0.z) + fabsf(g1.z - n1.z) + fabsf(g2.z - n2.z);
            r.w = fabsf(g0.w - n0.w) + fabsf(g1.w - n1.w) + fabsf(g2.w - n2.w);
            *(float4*)&res[row][4 * v] = r;
        }
    }
    __syncthreads();

    // ---- Phase 1b: reflect fixups (sources always inside the tile) ----
    if (by == 0) {                     // rows 0,1,2 <- rows 6,5,4
        for (int i = tid; i < 3 * 18; i += 256) {
            int r = i / 18, v = i - r * 18;
            *(float4*)&res[r][4 * v] = *(const float4*)&res[6 - r][4 * v];
        }
    }
    if (by == 15) {                    // rows 35,36,37 <- rows 33,32,31
        for (int i = tid; i < 3 * 18; i += 256) {
            int r = 35 + i / 18, v = i % 18;
            *(float4*)&res[r][4 * v] = *(const float4*)&res[68 - r][4 * v];
        }
    }
    __syncthreads();
    if (bx == 0) {                     // cols 1,2,3 <- cols 7,6,5
        for (int i = tid; i < RH * 3; i += 256) {
            int r = i / 3, c = 1 + i % 3;
            res[r][c] = res[r][8 - c];
        }
    }
    if (bx == 7) {                     // cols 68,69,70 <- cols 66,65,64
        for (int i = tid; i < RH * 3; i += 256) {
            int r = i / 3, c = 68 + i % 3;
            res[r][c] = res[r][134 - c];   // gx' = 1022 - gx  =>  c' = 134 - c
        }
    }
    __syncthreads();

    // ---- Phase 2': vertical sliding 7-sum (read each res row ONCE) ----
    for (int t = tid; t < 280; t += 256) {
        int col = t % 70 + 1;          // 1..70
        int y0  = (t / 70) * 8;        // 0,8,16,24

        float w1[7], w2[7];
        float s1 = 0.f, s2 = 0.f;
        #pragma unroll
        for (int d = 0; d < 7; d++) {
            float v = res[y0 + d][col];
            w1[d] = v; w2[d] = v * v;
            s1 += w1[d]; s2 += w2[d];
        }
        v1[y0][col] = s1; v2[y0][col] = s2;
        #pragma unroll
        for (int j = 1; j < 8; j++) {
            float v = res[y0 + 6 + j][col];
            s1 += v - w1[j - 1];
            s2 += v * v - w2[j - 1];
            v1[y0 + j][col] = s1;
            v2[y0 + j][col] = s2;
        }
    }
    __syncthreads();

    // ---- Phase 3': horizontal sliding 7-sum, 8 outputs per thread ----
    const int w  = tid >> 5, l = tid & 31;
    const int y  = (w & 3) * 8 + (l >> 2);       // 0..31
    const int g  = (w >> 2) * 4 + (l & 3);       // 0..7
    const int cb = 1 + 8 * g;                    // first tap column

    float a1[7], a2[7];
    float s1 = 0.f, s2 = 0.f;
    #pragma unroll
    for (int d = 0; d < 7; d++) {
        a1[d] = v1[y][cb + d];
        a2[d] = v2[y][cb + d];
        s1 += a1[d]; s2 += a2[d];
    }
    float accS = 0.f, accSum = 0.f, accSq = 0.f;
    #pragma unroll
    for (int j = 0; j < 8; j++) {
        float pw  = (s2 - s1 * s1 * (1.0f / 49.0f)) * (1.0f / 48.0f);
        float cen = res[y + 3][4 + 8 * g + j];
        accS   += fabsf(pw) * cen;
        accSum += cen;
        accSq  += cen * cen;
        if (j < 7) {
            s1 += v1[y][cb + 7 + j] - a1[j];
            s2 += v2[y][cb + 7 + j] - a2[j];
        }
    }

    // ---- block reduction -> global partials ----
    #pragma unroll
    for (int off = 16; off; off >>= 1) {
        accS   += __shfl_down_sync(0xFFFFFFFFu, accS,   off);
        accSum += __shfl_down_sync(0xFFFFFFFFu, accSum, off);
        accSq  += __shfl_down_sync(0xFFFFFFFFu, accSq,  off);
    }
    if (l == 0) { red[0][w] = accS; red[1][w] = accSum; red[2][w] = accSq; }
    __syncthreads();
    if (tid == 0) {
        float S = 0.f, Su = 0.f, Sq = 0.f;
        #pragma unroll
        for (int k = 0; k < 8; k++) { S += red[0][k]; Su += red[1][k]; Sq += red[2][k]; }
        int tile = by * 8 + bx;
        g_pS    [b * TILES_PER_IMG + tile] = S;
        g_psum  [b * TILES_PER_IMG + tile] = Su;
        g_psumsq[b * TILES_PER_IMG + tile] = Sq;

        __threadfence();
        unsigned ticket = atomicAdd(&g_count, 1u);
        s_last = (ticket == NBLOCKS - 1);
    }
    __syncthreads();

    // ---- fused epilogue: last block reduces all partials ----
    if (s_last) {
        double tot = 0.0;
        for (int bb = w; bb < B; bb += 8) {
            double dS = 0.0, du = 0.0, dq = 0.0;
            #pragma unroll
            for (int k = 0; k < 4; k++) {
                int idx = bb * TILES_PER_IMG + l + 32 * k;
                dS += (double)g_pS    [idx];
                du += (double)g_psum  [idx];
                dq += (double)g_psumsq[idx];
            }
            #pragma unroll
            for (int off = 16; off; off >>= 1) {
                dS += __shfl_down_sync(0xFFFFFFFFu, dS, off);
                du += __shfl_down_sync(0xFFFFFFFFu, du, off);
                dq += __shfl_down_sync(0xFFFFFFFFu, dq, off);
            }
            if (l == 0) {
                const double N = (double)(H * W);
                double var = (dq - du * du / N) / (N - 1.0);
                if (var < 0.0) var = 0.0;
                float pw = powf((float)var, 0.2f);   // fp32 pow: fast, err ~1e-7
                tot += (double)pw * dS;
            }
        }
        if (l == 0) shd[w] = tot;
        __syncthreads();
        if (tid == 0) {
            double v = 0.0;
            #pragma unroll
            for (int k = 0; k < 8; k++) v += shd[k];
            out[0] = (float)(v / ((double)B * C * H * W));
            g_count = 0;                 // reset for next replay
        }
    }
}

extern "C" void kernel_launch(void* const* d_in, const int* in_sizes, int n_in,
                              void* d_out, int out_size) {
    const float* net = (const float*)d_in[0];   // net_output
    const float* gt  = (const float*)d_in[1];   // gt
    float* out = (float*)d_out;

    dim3 grid(W / TX, H / TY, B);               // 8 x 16 x 32
    ldl_main<<<grid, 256>>>(net, gt, out);
}

// round 8
// speedup vs baseline: 1.3498x; 1.0263x over previous
#include <cuda_runtime.h>
#include <math.h>

#define B    32
#define C    3
#define H    512
#define W    512
#define TX   64               // output tile width
#define TY   32               // output tile height
#define RW   76               // res smem row stride (float4-aligned, 72 used)
#define RH   38               // res rows (TY + 6)
#define VW   73               // v1/v2 row stride (odd -> conflict-free column walks)
#define TILES_PER_IMG 128     // (512/64)*(512/32)

__device__ float g_psum  [B * TILES_PER_IMG];
__device__ float g_psumsq[B * TILES_PER_IMG];
__device__ float g_pS    [B * TILES_PER_IMG];

__global__ __launch_bounds__(256, 6)
void ldl_main(const float* __restrict__ net, const float* __restrict__ gt) {
    __shared__ float res[RH][RW];      // residual, col c <-> gx = 64*bx-4+c
    __shared__ float v1 [TY][VW];      // vertical 7-sums of r   (cols 1..70)
    __shared__ float v2 [TY][VW];      // vertical 7-sums of r^2
    __shared__ float red[3][8];

    const int bx  = blockIdx.x;        // 0..7
    const int by  = blockIdx.y;        // 0..15
    const int b   = blockIdx.z;
    const int tid = threadIdx.x;

    const int x0a = TX * bx - 4;       // global x of smem col 0 (16B aligned)
    const int y0a = TY * by - 3;       // global y of smem row 0

    const int HW = H * W;
    const float* nb = net + b * (C * HW);
    const float* gb = gt  + b * (C * HW);

    // ---- Phase 1: vectorized residual load (skip out-of-range vec4s) ----
    for (int i = tid; i < RH * 18; i += 256) {
        int row = i / 18, v = i - row * 18;
        int gy = y0a + row;
        int gx = x0a + 4 * v;          // multiple of 4 -> vec4 fully in or out
        if ((unsigned)gy < H && (unsigned)gx < W) {
            int p = gy * W + gx;
            float4 n0 = *(const float4*)(nb + p);
            float4 n1 = *(const float4*)(nb + p + HW);
            float4 n2 = *(const float4*)(nb + p + 2 * HW);
            float4 g0 = *(const float4*)(gb + p);
            float4 g1 = *(const float4*)(gb + p + HW);
            float4 g2 = *(const float4*)(gb + p + 2 * HW);
            float4 r;
            r.x = fabsf(g0.x - n0.x) + fabsf(g1.x - n1.x) + fabsf(g2.x - n2.x);
            r.y = fabsf(g0.y - n0.y) + fabsf(g1.y - n1.y) + fabsf(g2.y - n2.y);
            r.z = fabsf(g0.z - n0.z) + fabsf(g1.z - n1.z) + fabsf(g2.z - n2.z);
            r.w = fabsf(g0.w - n0.w) + fabsf(g1.w - n1.w) + fabsf(g2.w - n2.w);
            *(float4*)&res[row][4 * v] = r;
        }
    }
    __syncthreads();

    // ---- Phase 1b: reflect fixups (sources always inside the tile) ----
    if (by == 0) {                     // rows 0,1,2 <- rows 6,5,4
        for (int i = tid; i < 3 * 18; i += 256) {
            int r = i / 18, v = i - r * 18;
            *(float4*)&res[r][4 * v] = *(const float4*)&res[6 - r][4 * v];
        }
    }
    if (by == 15) {                    // rows 35,36,37 <- rows 33,32,31
        for (int i = tid; i < 3 * 18; i += 256) {
            int r = 35 + i / 18, v = i % 18;
            *(float4*)&res[r][4 * v] = *(const float4*)&res[68 - r][4 * v];
        }
    }
    __syncthreads();
    if (bx == 0) {                     // cols 1,2,3 <- cols 7,6,5
        for (int i = tid; i < RH * 3; i += 256) {
            int r = i / 3, c = 1 + i % 3;
            res[r][c] = res[r][8 - c];
        }
    }
    if (bx == 7) {                     // cols 68,69,70 <- cols 66,65,64
        for (int i = tid; i < RH * 3; i += 256) {
            int r = i / 3, c = 68 + i % 3;
            res[r][c] = res[r][134 - c];   // gx' = 1022 - gx  =>  c' = 134 - c
        }
    }
    __syncthreads();

    // ---- Phase 2': vertical sliding 7-sum (read each res row ONCE) ----
    for (int t = tid; t < 280; t += 256) {
        int col = t % 70 + 1;          // 1..70
        int y0  = (t / 70) * 8;        // 0,8,16,24

        float w1[7], w2[7];
        float s1 = 0.f, s2 = 0.f;
        #pragma unroll
        for (int d = 0; d < 7; d++) {
            float v = res[y0 + d][col];
            w1[d] = v; w2[d] = v * v;
            s1 += w1[d]; s2 += w2[d];
        }
        v1[y0][col] = s1; v2[y0][col] = s2;
        #pragma unroll
        for (int j = 1; j < 8; j++) {
            float v = res[y0 + 6 + j][col];
            s1 += v - w1[j - 1];
            s2 += v * v - w2[j - 1];
            v1[y0 + j][col] = s1;
            v2[y0 + j][col] = s2;
        }
    }
    __syncthreads();

    // ---- Phase 3': horizontal sliding 7-sum, 8 outputs per thread ----
    const int w  = tid >> 5, l = tid & 31;
    const int y  = (w & 3) * 8 + (l >> 2);       // 0..31
    const int g  = (w >> 2) * 4 + (l & 3);       // 0..7
    const int cb = 1 + 8 * g;                    // first tap column

    float a1[7], a2[7];
    float s1 = 0.f, s2 = 0.f;
    #pragma unroll
    for (int d = 0; d < 7; d++) {
        a1[d] = v1[y][cb + d];
        a2[d] = v2[y][cb + d];
        s1 += a1[d]; s2 += a2[d];
    }
    float accS = 0.f, accSum = 0.f, accSq = 0.f;
    #pragma unroll
    for (int j = 0; j < 8; j++) {
        float pw  = (s2 - s1 * s1 * (1.0f / 49.0f)) * (1.0f / 48.0f);
        float cen = res[y + 3][4 + 8 * g + j];
        accS   += fabsf(pw) * cen;
        accSum += cen;
        accSq  += cen * cen;
        if (j < 7) {
            s1 += v1[y][cb + 7 + j] - a1[j];
            s2 += v2[y][cb + 7 + j] - a2[j];
        }
    }

    // ---- block reduction -> global partials ----
    #pragma unroll
    for (int off = 16; off; off >>= 1) {
        accS   += __shfl_down_sync(0xFFFFFFFFu, accS,   off);
        accSum += __shfl_down_sync(0xFFFFFFFFu, accSum, off);
        accSq  += __shfl_down_sync(0xFFFFFFFFu, accSq,  off);
    }
    if (l == 0) { red[0][w] = accS; red[1][w] = accSum; red[2][w] = accSq; }
    __syncthreads();
    if (tid == 0) {
        float S = 0.f, Su = 0.f, Sq = 0.f;
        #pragma unroll
        for (int k = 0; k < 8; k++) { S += red[0][k]; Su += red[1][k]; Sq += red[2][k]; }
        int tile = by * 8 + bx;
        g_pS    [b * TILES_PER_IMG + tile] = S;
        g_psum  [b * TILES_PER_IMG + tile] = Su;
        g_psumsq[b * TILES_PER_IMG + tile] = Sq;
    }
}

// Single-block epilogue: warp w handles batches w, w+8, w+16, w+24 (powf in
// parallel across warps); double accumulation keeps determinism/accuracy.
__global__ __launch_bounds__(256)
void ldl_final(float* __restrict__ out) {
    __shared__ double shd[8];
    const int tid = threadIdx.x;
    const int w = tid >> 5, l = tid & 31;

    double tot = 0.0;
    for (int bb = w; bb < B; bb += 8) {
        double dS = 0.0, du = 0.0, dq = 0.0;
        #pragma unroll
        for (int k = 0; k < 4; k++) {
            int idx = bb * TILES_PER_IMG + l + 32 * k;
            dS += (double)g_pS    [idx];
            du += (double)g_psum  [idx];
            dq += (double)g_psumsq[idx];
        }
        #pragma unroll
        for (int off = 16; off; off >>= 1) {
            dS += __shfl_down_sync(0xFFFFFFFFu, dS, off);
            du += __shfl_down_sync(0xFFFFFFFFu, du, off);
            dq += __shfl_down_sync(0xFFFFFFFFu, dq, off);
        }
        if (l == 0) {
            const double N = (double)(H * W);
            double var = (dq - du * du / N) / (N - 1.0);
            if (var < 0.0) var = 0.0;
            float pw = powf((float)var, 0.2f);   // fp32 pow: fast, err ~1e-7
            tot += (double)pw * dS;
        }
    }
    if (l == 0) shd[w] = tot;
    __syncthreads();
    if (tid == 0) {
        double v = 0.0;
        #pragma unroll
        for (int k = 0; k < 8; k++) v += shd[k];
        out[0] = (float)(v / ((double)B * C * H * W));
    }
}

extern "C" void kernel_launch(void* const* d_in, const int* in_sizes, int n_in,
                              void* d_out, int out_size) {
    const float* net = (const float*)d_in[0];   // net_output
    const float* gt  = (const float*)d_in[1];   // gt
    float* out = (float*)d_out;

    dim3 grid(W / TX, H / TY, B);               // 8 x 16 x 32
    ldl_main<<<grid, 256>>>(net, gt);
    ldl_final<<<1, 256>>>(out);
}

// round 9
// speedup vs baseline: 1.4789x; 1.0957x over previous
#include <cuda_runtime.h>
#include <math.h>

#define B    32
#define C    3
#define H    512
#define W    512
#define TX   64               // output tile width
#define TY   32               // output tile height
#define RW   76               // res smem row stride (float4-aligned, 72 used)
#define RH   38               // res rows (TY + 6)
#define VW   73               // v1/v2 row stride (odd -> conflict-free column walks)
#define TILES_PER_IMG 128     // (512/64)*(512/32)
#define NBLOCKS (8 * 16 * 32) // 4096

__device__ float g_psum  [B * TILES_PER_IMG];
__device__ float g_psumsq[B * TILES_PER_IMG];
__device__ float g_pS    [B * TILES_PER_IMG];
__device__ unsigned g_count = 0;

// Release-ordered ticket: ATOMG.STRONG.GPU at L2 — orders prior stores without
// the CCTL.IVALL L1 flush that __threadfence() emits (the R7 regression).
__device__ __forceinline__ unsigned ticket_acq_rel(unsigned* p) {
    unsigned old;
    asm volatile("atom.acq_rel.gpu.add.u32 %0, [%1], 1;"
                 : "=r"(old) : "l"(p) : "memory");
    return old;
}

__global__ __launch_bounds__(256, 6)
void ldl_main(const float* __restrict__ net, const float* __restrict__ gt,
              float* __restrict__ out) {
    __shared__ float res[RH][RW];      // residual, col c <-> gx = 64*bx-4+c
    __shared__ float v1 [TY][VW];      // vertical 7-sums of r   (cols 1..70)
    __shared__ float v2 [TY][VW];      // vertical 7-sums of r^2
    __shared__ float red[3][8];
    __shared__ double shd[B];
    __shared__ int s_last;

    const int bx  = blockIdx.x;        // 0..7
    const int by  = blockIdx.y;        // 0..15
    const int b   = blockIdx.z;
    const int tid = threadIdx.x;

    const int x0a = TX * bx - 4;       // global x of smem col 0 (16B aligned)
    const int y0a = TY * by - 3;       // global y of smem row 0

    const int HW = H * W;
    const float* nb = net + b * (C * HW);
    const float* gb = gt  + b * (C * HW);

    // ---- Phase 1: vectorized residual load (skip out-of-range vec4s) ----
    for (int i = tid; i < RH * 18; i += 256) {
        int row = i / 18, v = i - row * 18;
        int gy = y0a + row;
        int gx = x0a + 4 * v;          // multiple of 4 -> vec4 fully in or out
        if ((unsigned)gy < H && (unsigned)gx < W) {
            int p = gy * W + gx;
            float4 n0 = *(const float4*)(nb + p);
            float4 n1 = *(const float4*)(nb + p + HW);
            float4 n2 = *(const float4*)(nb + p + 2 * HW);
            float4 g0 = *(const float4*)(gb + p);
            float4 g1 = *(const float4*)(gb + p + HW);
            float4 g2 = *(const float4*)(gb + p + 2 * HW);
            float4 r;
            r.x = fabsf(g0.x - n0.x) + fabsf(g1.x - n1.x) + fabsf(g2.x - n2.x);
            r.y = fabsf(g0.y - n0.y) + fabsf(g1.y - n1.y) + fabsf(g2.y - n2.y);
            r.z = fabsf(g0.z - n0.z) + fabsf(g1.z - n1.z) + fabsf(g2.z - n2.z);
            r.w = fabsf(g0.w - n0.w) + fabsf(g1.w - n1.w) + fabsf(g2.w - n2.w);
            *(float4*)&res[row][4 * v] = r;
        }
    }
    __syncthreads();

    // ---- Phase 1b: reflect fixups (sources always inside the tile) ----
    if (by == 0) {                     // rows 0,1,2 <- rows 6,5,4
        for (int i = tid; i < 3 * 18; i += 256) {
            int r = i / 18, v = i - r * 18;
            *(float4*)&res[r][4 * v] = *(const float4*)&res[6 - r][4 * v];
        }
    }
    if (by == 15) {                    // rows 35,36,37 <- rows 33,32,31
        for (int i = tid; i < 3 * 18; i += 256) {
            int r = 35 + i / 18, v = i % 18;
            *(float4*)&res[r][4 * v] = *(const float4*)&res[68 - r][4 * v];
        }
    }
    __syncthreads();
    if (bx == 0) {                     // cols 1,2,3 <- cols 7,6,5
        for (int i = tid; i < RH * 3; i += 256) {
            int r = i / 3, c = 1 + i % 3;
            res[r][c] = res[r][8 - c];
        }
    }
    if (bx == 7) {                     // cols 68,69,70 <- cols 66,65,64
        for (int i = tid; i < RH * 3; i += 256) {
            int r = i / 3, c = 68 + i % 3;
            res[r][c] = res[r][134 - c];   // gx' = 1022 - gx  =>  c' = 134 - c
        }
    }
    __syncthreads();

    // ---- Phase 2': vertical sliding 7-sum (read each res row ONCE) ----
    for (int t = tid; t < 280; t += 256) {
        int col = t % 70 + 1;          // 1..70
        int y0  = (t / 70) * 8;        // 0,8,16,24

        float w1[7], w2[7];
        float s1 = 0.f, s2 = 0.f;
        #pragma unroll
        for (int d = 0; d < 7; d++) {
            float v = res[y0 + d][col];
            w1[d] = v; w2[d] = v * v;
            s1 += w1[d]; s2 += w2[d];
        }
        v1[y0][col] = s1; v2[y0][col] = s2;
        #pragma unroll
        for (int j = 1; j < 8; j++) {
            float v = res[y0 + 6 + j][col];
            s1 += v - w1[j - 1];
            s2 += v * v - w2[j - 1];
            v1[y0 + j][col] = s1;
            v2[y0 + j][col] = s2;
        }
    }
    __syncthreads();

    // ---- Phase 3': horizontal sliding 7-sum, 8 outputs per thread ----
    const int w  = tid >> 5, l = tid & 31;
    const int y  = (w & 3) * 8 + (l >> 2);       // 0..31
    const int g  = (w >> 2) * 4 + (l & 3);       // 0..7
    const int cb = 1 + 8 * g;                    // first tap column

    float a1[7], a2[7];
    float s1 = 0.f, s2 = 0.f;
    #pragma unroll
    for (int d = 0; d < 7; d++) {
        a1[d] = v1[y][cb + d];
        a2[d] = v2[y][cb + d];
        s1 += a1[d]; s2 += a2[d];
    }
    float accS = 0.f, accSum = 0.f, accSq = 0.f;
    #pragma unroll
    for (int j = 0; j < 8; j++) {
        float pw  = (s2 - s1 * s1 * (1.0f / 49.0f)) * (1.0f / 48.0f);
        float cen = res[y + 3][4 + 8 * g + j];
        accS   += fabsf(pw) * cen;
        accSum += cen;
        accSq  += cen * cen;
        if (j < 7) {
            s1 += v1[y][cb + 7 + j] - a1[j];
            s2 += v2[y][cb + 7 + j] - a2[j];
        }
    }

    // ---- block reduction -> global partials ----
    #pragma unroll
    for (int off = 16; off; off >>= 1) {
        accS   += __shfl_down_sync(0xFFFFFFFFu, accS,   off);
        accSum += __shfl_down_sync(0xFFFFFFFFu, accSum, off);
        accSq  += __shfl_down_sync(0xFFFFFFFFu, accSq,  off);
    }
    if (l == 0) { red[0][w] = accS; red[1][w] = accSum; red[2][w] = accSq; }
    __syncthreads();
    if (tid == 0) {
        float S = 0.f, Su = 0.f, Sq = 0.f;
        #pragma unroll
        for (int k = 0; k < 8; k++) { S += red[0][k]; Su += red[1][k]; Sq += red[2][k]; }
        int tile = by * 8 + bx;
        g_pS    [b * TILES_PER_IMG + tile] = S;
        g_psum  [b * TILES_PER_IMG + tile] = Su;
        g_psumsq[b * TILES_PER_IMG + tile] = Sq;

        unsigned ticket = ticket_acq_rel(&g_count);   // release: orders stores, no L1 flush
        s_last = (ticket == NBLOCKS - 1);
    }
    __syncthreads();

    // ---- fused epilogue: last block, fully parallel over batches ----
    // Warp w owns batches 4w..4w+3; 8 lanes per batch, 16 partials per lane.
    if (s_last) {
        const int bb = 4 * w + (l >> 3);    // batch 0..31
        const int k  = l & 7;               // sub-lane 0..7
        const int base = bb * TILES_PER_IMG + k * 16;

        double dS = 0.0, du = 0.0, dq = 0.0;
        #pragma unroll
        for (int j = 0; j < 16; j++) {
            dS += (double)__ldcg(&g_pS    [base + j]);   // L2-only: sees released data
            du += (double)__ldcg(&g_psum  [base + j]);
            dq += (double)__ldcg(&g_psumsq[base + j]);
        }
        #pragma unroll
        for (int off = 4; off; off >>= 1) {              // reduce 8-lane group
            dS += __shfl_xor_sync(0xFFFFFFFFu, dS, off);
            du += __shfl_xor_sync(0xFFFFFFFFu, du, off);
            dq += __shfl_xor_sync(0xFFFFFFFFu, dq, off);
        }
        if (k == 0) {
            const double N = (double)(H * W);
            double var = (dq - du * du / N) / (N - 1.0);
            if (var < 0.0) var = 0.0;
            float pw = powf((float)var, 0.2f);           // fp32 pow, err ~1e-7
            shd[bb] = (double)pw * dS;
        }
        __syncthreads();
        if (w == 0) {
            double v = shd[l];
            #pragma unroll
            for (int off = 16; off; off >>= 1)
                v += __shfl_down_sync(0xFFFFFFFFu, v, off);
            if (l == 0) {
                out[0] = (float)(v / ((double)B * C * H * W));
                g_count = 0;                 // reset for next graph replay
            }
        }
    }
}

extern "C" void kernel_launch(void* const* d_in, const int* in_sizes, int n_in,
                              void* d_out, int out_size) {
    const float* net = (const float*)d_in[0];   // net_output
    const float* gt  = (const float*)d_in[1];   // gt
    float* out = (float*)d_out;

    dim3 grid(W / TX, H / TY, B);               // 8 x 16 x 32
    ldl_main<<<grid, 256>>>(net, gt, out);
}

// round 10
// speedup vs baseline: 1.5321x; 1.0360x over previous
#include <cuda_runtime.h>
#include <math.h>

#define B    32
#define C    3
#define H    512
#define W    512
#define TX   64               // output tile width
#define TY   32               // output tile height
#define RW   76               // res smem row stride (float4-aligned, 72 used)
#define RH   38               // res rows (TY + 6)
#define VW   73               // v1/v2 row stride (odd -> conflict-free column walks)
#define TILES_PER_IMG 128     // (512/64)*(512/32)

__device__ float g_psum  [B * TILES_PER_IMG];
__device__ float g_psumsq[B * TILES_PER_IMG];
__device__ float g_pS    [B * TILES_PER_IMG];

__global__ __launch_bounds__(256, 6)
void ldl_main(const float* __restrict__ net, const float* __restrict__ gt) {
    __shared__ float res[RH][RW];      // residual, col c <-> gx = 64*bx-4+c
    __shared__ float v1 [TY][VW];      // vertical 7-sums of r   (cols 1..70)
    __shared__ float v2 [TY][VW];      // vertical 7-sums of r^2
    __shared__ float red[3][8];

    const int bx  = blockIdx.x;        // 0..7
    const int by  = blockIdx.y;        // 0..15
    const int b   = blockIdx.z;
    const int tid = threadIdx.x;

    const int x0a = TX * bx - 4;       // global x of smem col 0 (16B aligned)
    const int y0a = TY * by - 3;       // global y of smem row 0

    const int HW = H * W;
    const float* nb = net + b * (C * HW);
    const float* gb = gt  + b * (C * HW);

    // ---- Phase 1: vectorized residual load (skip out-of-range vec4s) ----
    for (int i = tid; i < RH * 18; i += 256) {
        int row = i / 18, v = i - row * 18;
        int gy = y0a + row;
        int gx = x0a + 4 * v;          // multiple of 4 -> vec4 fully in or out
        if ((unsigned)gy < H && (unsigned)gx < W) {
            int p = gy * W + gx;
            float4 n0 = *(const float4*)(nb + p);
            float4 n1 = *(const float4*)(nb + p + HW);
            float4 n2 = *(const float4*)(nb + p + 2 * HW);
            float4 g0 = *(const float4*)(gb + p);
            float4 g1 = *(const float4*)(gb + p + HW);
            float4 g2 = *(const float4*)(gb + p + 2 * HW);
            float4 r;
            r.x = fabsf(g0.x - n0.x) + fabsf(g1.x - n1.x) + fabsf(g2.x - n2.x);
            r.y = fabsf(g0.y - n0.y) + fabsf(g1.y - n1.y) + fabsf(g2.y - n2.y);
            r.z = fabsf(g0.z - n0.z) + fabsf(g1.z - n1.z) + fabsf(g2.z - n2.z);
            r.w = fabsf(g0.w - n0.w) + fabsf(g1.w - n1.w) + fabsf(g2.w - n2.w);
            *(float4*)&res[row][4 * v] = r;
        }
    }
    __syncthreads();

    // ---- Phase 1b: reflect fixups (sources always inside the tile) ----
    if (by == 0) {                     // rows 0,1,2 <- rows 6,5,4
        for (int i = tid; i < 3 * 18; i += 256) {
            int r = i / 18, v = i - r * 18;
            *(float4*)&res[r][4 * v] = *(const float4*)&res[6 - r][4 * v];
        }
    }
    if (by == 15) {                    // rows 35,36,37 <- rows 33,32,31
        for (int i = tid; i < 3 * 18; i += 256) {
            int r = 35 + i / 18, v = i % 18;
            *(float4*)&res[r][4 * v] = *(const float4*)&res[68 - r][4 * v];
        }
    }
    __syncthreads();
    if (bx == 0) {                     // cols 1,2,3 <- cols 7,6,5
        for (int i = tid; i < RH * 3; i += 256) {
            int r = i / 3, c = 1 + i % 3;
            res[r][c] = res[r][8 - c];
        }
    }
    if (bx == 7) {                     // cols 68,69,70 <- cols 66,65,64
        for (int i = tid; i < RH * 3; i += 256) {
            int r = i / 3, c = 68 + i % 3;
            res[r][c] = res[r][134 - c];   // gx' = 1022 - gx  =>  c' = 134 - c
        }
    }
    __syncthreads();

    // ---- Phase 2': vertical sliding 7-sum (read each res row ONCE) ----
    for (int t = tid; t < 280; t += 256) {
        int col = t % 70 + 1;          // 1..70
        int y0  = (t / 70) * 8;        // 0,8,16,24

        float w1[7], w2[7];
        float s1 = 0.f, s2 = 0.f;
        #pragma unroll
        for (int d = 0; d < 7; d++) {
            float v = res[y0 + d][col];
            w1[d] = v; w2[d] = v * v;
            s1 += w1[d]; s2 += w2[d];
        }
        v1[y0][col] = s1; v2[y0][col] = s2;
        #pragma unroll
        for (int j = 1; j < 8; j++) {
            float v = res[y0 + 6 + j][col];
            s1 += v - w1[j - 1];
            s2 += v * v - w2[j - 1];
            v1[y0 + j][col] = s1;
            v2[y0 + j][col] = s2;
        }
    }
    __syncthreads();

    // ---- Phase 3': horizontal sliding 7-sum, 8 outputs per thread ----
    const int w  = tid >> 5, l = tid & 31;
    const int y  = (w & 3) * 8 + (l >> 2);       // 0..31
    const int g  = (w >> 2) * 4 + (l & 3);       // 0..7
    const int cb = 1 + 8 * g;                    // first tap column

    float a1[7], a2[7];
    float s1 = 0.f, s2 = 0.f;
    #pragma unroll
    for (int d = 0; d < 7; d++) {
        a1[d] = v1[y][cb + d];
        a2[d] = v2[y][cb + d];
        s1 += a1[d]; s2 += a2[d];
    }
    float accS = 0.f, accSum = 0.f, accSq = 0.f;
    #pragma unroll
    for (int j = 0; j < 8; j++) {
        float pw  = (s2 - s1 * s1 * (1.0f / 49.0f)) * (1.0f / 48.0f);
        float cen = res[y + 3][4 + 8 * g + j];
        accS   += fabsf(pw) * cen;
        accSum += cen;
        accSq  += cen * cen;
        if (j < 7) {
            s1 += v1[y][cb + 7 + j] - a1[j];
            s2 += v2[y][cb + 7 + j] - a2[j];
        }
    }

    // ---- block reduction -> global partials ----
    #pragma unroll
    for (int off = 16; off; off >>= 1) {
        accS   += __shfl_down_sync(0xFFFFFFFFu, accS,   off);
        accSum += __shfl_down_sync(0xFFFFFFFFu, accSum, off);
        accSq  += __shfl_down_sync(0xFFFFFFFFu, accSq,  off);
    }
    if (l == 0) { red[0][w] = accS; red[1][w] = accSum; red[2][w] = accSq; }
    __syncthreads();
    if (tid == 0) {
        float S = 0.f, Su = 0.f, Sq = 0.f;
        #pragma unroll
        for (int k = 0; k < 8; k++) { S += red[0][k]; Su += red[1][k]; Sq += red[2][k]; }
        int tile = by * 8 + bx;
        g_pS    [b * TILES_PER_IMG + tile] = S;
        g_psum  [b * TILES_PER_IMG + tile] = Su;
        g_psumsq[b * TILES_PER_IMG + tile] = Sq;
    }
}

// Single-block epilogue, fully parallel over batches:
// warp w owns batches 4w..4w+3; 8 lanes per batch, 16 partials per lane.
// All 32 powf's execute concurrently (distinct lanes of different warps).
__global__ __launch_bounds__(256)
void ldl_final(float* __restrict__ out) {
    __shared__ double shd[B];
    const int tid = threadIdx.x;
    const int w = tid >> 5, l = tid & 31;

    const int bb = 4 * w + (l >> 3);    // batch 0..31
    const int k  = l & 7;               // sub-lane 0..7
    const int base = bb * TILES_PER_IMG + k * 16;

    double dS = 0.0, du = 0.0, dq = 0.0;
    #pragma unroll
    for (int j = 0; j < 16; j++) {
        dS += (double)g_pS    [base + j];
        du += (double)g_psum  [base + j];
        dq += (double)g_psumsq[base + j];
    }
    #pragma unroll
    for (int off = 4; off; off >>= 1) {  // reduce 8-lane group
        dS += __shfl_xor_sync(0xFFFFFFFFu, dS, off);
        du += __shfl_xor_sync(0xFFFFFFFFu, du, off);
        dq += __shfl_xor_sync(0xFFFFFFFFu, dq, off);
    }
    if (k == 0) {
        const double N = (double)(H * W);
        double var = (dq - du * du / N) / (N - 1.0);
        if (var < 0.0) var = 0.0;
        float pw = powf((float)var, 0.2f);   // fp32 pow, err ~1e-7
        shd[bb] = (double)pw * dS;
    }
    __syncthreads();
    if (w == 0) {
        double v = shd[l];
        #pragma unroll
        for (int off = 16; off; off >>= 1)
            v += __shfl_down_sync(0xFFFFFFFFu, v, off);
        if (l == 0)
            out[0] = (float)(v / ((double)B * C * H * W));
    }
}

extern "C" void kernel_launch(void* const* d_in, const int* in_sizes, int n_in,
                              void* d_out, int out_size) {
    const float* net = (const float*)d_in[0];   // net_output
    const float* gt  = (const float*)d_in[1];   // gt
    float* out = (float*)d_out;

    dim3 grid(W / TX, H / TY, B);               // 8 x 16 x 32
    ldl_main<<<grid, 256>>>(net, gt);
    ldl_final<<<1, 256>>>(out);
}